// round 1
// baseline (speedup 1.0000x reference)
#include <cuda_runtime.h>
#include <cstdint>

#define BATCH 8
#define SEQ   2048
#define CH    512
#define ROWS  (BATCH * SEQ)   // 16384
#define SCALE 0.25f

// Scratch: projected Q/K/V and the attention score matrix S.
__device__ float g_Qp[(size_t)ROWS * CH];
__device__ float g_Kp[(size_t)ROWS * CH];
__device__ float g_Vp[(size_t)ROWS * CH];
__device__ float g_S[(size_t)BATCH * SEQ * SEQ];

// ---------------------------------------------------------------------------
// Generic 128x128 tile SGEMM body, BK=8, 256 threads, 8x8 per thread.
// TRANS_B=false: C = A[M,K] * B[K,N]      (B row-major)
// TRANS_B=true : C = A[M,K] * B[N,K]^T    (B rows indexed by output column)
// Fragment layout: each thread owns rows {ty*4..+3, 64+ty*4..+3} and
// cols {tx*4..+3, 64+tx*4..+3}  -> conflict-free LDS.128 reads.
// ---------------------------------------------------------------------------
template<bool TRANS_B, bool HAS_BIAS>
__device__ __forceinline__ void gemm128(
    const float* __restrict__ A, const float* __restrict__ Bm,
    float* __restrict__ C, const float* __restrict__ bias,
    int K, int N, float alpha)
{
    __shared__ __align__(16) float As[8][128];
    __shared__ __align__(16) float Bs[8][128];

    const int tid = threadIdx.x;
    const int tx  = tid & 15;
    const int ty  = tid >> 4;
    const int rowBlock = blockIdx.y * 128;
    const int colBlock = blockIdx.x * 128;

    // A-tile load mapping: 128 rows x 8 k, one float4 per thread
    const int aRow = tid >> 1;
    const int aCol = (tid & 1) * 4;
    // B-tile (NN) load mapping: 8 k-rows x 128 cols, one float4 per thread
    const int bRow = tid >> 5;
    const int bCol = (tid & 31) * 4;

    float acc[8][8];
#pragma unroll
    for (int i = 0; i < 8; i++)
#pragma unroll
        for (int j = 0; j < 8; j++) acc[i][j] = 0.f;

    for (int k0 = 0; k0 < K; k0 += 8) {
        float4 a4 = *(const float4*)(A + (size_t)(rowBlock + aRow) * K + k0 + aCol);
        As[aCol + 0][aRow] = a4.x;
        As[aCol + 1][aRow] = a4.y;
        As[aCol + 2][aRow] = a4.z;
        As[aCol + 3][aRow] = a4.w;
        if (TRANS_B) {
            float4 b4 = *(const float4*)(Bm + (size_t)(colBlock + aRow) * K + k0 + aCol);
            Bs[aCol + 0][aRow] = b4.x;
            Bs[aCol + 1][aRow] = b4.y;
            Bs[aCol + 2][aRow] = b4.z;
            Bs[aCol + 3][aRow] = b4.w;
        } else {
            float4 b4 = *(const float4*)(Bm + (size_t)(k0 + bRow) * N + colBlock + bCol);
            *(float4*)&Bs[bRow][bCol] = b4;
        }
        __syncthreads();
#pragma unroll
        for (int kk = 0; kk < 8; kk++) {
            float4 a0 = *(const float4*)&As[kk][ty * 4];
            float4 a1 = *(const float4*)&As[kk][64 + ty * 4];
            float4 b0 = *(const float4*)&Bs[kk][tx * 4];
            float4 b1 = *(const float4*)&Bs[kk][64 + tx * 4];
            float a[8] = {a0.x, a0.y, a0.z, a0.w, a1.x, a1.y, a1.z, a1.w};
            float b[8] = {b0.x, b0.y, b0.z, b0.w, b1.x, b1.y, b1.z, b1.w};
#pragma unroll
            for (int i = 0; i < 8; i++)
#pragma unroll
                for (int j = 0; j < 8; j++)
                    acc[i][j] += a[i] * b[j];
        }
        __syncthreads();
    }

#pragma unroll
    for (int i = 0; i < 8; i++) {
        int ri = rowBlock + ((i < 4) ? (ty * 4 + i) : (64 + ty * 4 + (i - 4)));
#pragma unroll
        for (int jj = 0; jj < 2; jj++) {
            int cbase = colBlock + jj * 64 + tx * 4;
            float4 o;
            o.x = acc[i][jj * 4 + 0] * alpha;
            o.y = acc[i][jj * 4 + 1] * alpha;
            o.z = acc[i][jj * 4 + 2] * alpha;
            o.w = acc[i][jj * 4 + 3] * alpha;
            if (HAS_BIAS) {
                o.x += bias[cbase + 0];
                o.y += bias[cbase + 1];
                o.z += bias[cbase + 2];
                o.w += bias[cbase + 3];
            }
            *(float4*)(C + (size_t)ri * N + cbase) = o;
        }
    }
}

// ---------------------------------------------------------------------------
// Stage 1: fused Q/K/V projection. z selects which projection.
// grid: (CH/128=4, ROWS/128=128, 3)
// ---------------------------------------------------------------------------
__global__ __launch_bounds__(256) void proj_kernel(
    const float* __restrict__ q, const float* __restrict__ k, const float* __restrict__ v,
    const float* __restrict__ Wq, const float* __restrict__ bq,
    const float* __restrict__ Wk, const float* __restrict__ bk,
    const float* __restrict__ Wv, const float* __restrict__ bv)
{
    const float *A, *W, *bias;
    float* C;
    if (blockIdx.z == 0)      { A = q; W = Wq; bias = bq; C = g_Qp; }
    else if (blockIdx.z == 1) { A = k; W = Wk; bias = bk; C = g_Kp; }
    else                      { A = v; W = Wv; bias = bv; C = g_Vp; }
    gemm128<false, true>(A, W, C, bias, CH, CH, 1.0f);
}

// ---------------------------------------------------------------------------
// Stage 2: S = Qp * Kp^T * SCALE per batch.   grid: (16, 16, 8)
// ---------------------------------------------------------------------------
__global__ __launch_bounds__(256) void qk_kernel()
{
    size_t boff = (size_t)blockIdx.z * SEQ * CH;
    gemm128<true, false>(g_Qp + boff, g_Kp + boff,
                         g_S + (size_t)blockIdx.z * SEQ * SEQ,
                         nullptr, CH, SEQ, SCALE);
}

// ---------------------------------------------------------------------------
// Stage 3: row softmax over S, in place. grid: 16384 blocks x 256 threads.
// ---------------------------------------------------------------------------
__global__ __launch_bounds__(256) void softmax_kernel()
{
    __shared__ float red[8];
    float* row = g_S + (size_t)blockIdx.x * SEQ;
    const int tid = threadIdx.x;

    float vals[8];
    float m = -3.0e38f;
#pragma unroll
    for (int i = 0; i < 8; i++) {
        vals[i] = row[tid + i * 256];
        m = fmaxf(m, vals[i]);
    }
#pragma unroll
    for (int o = 16; o; o >>= 1) m = fmaxf(m, __shfl_xor_sync(0xffffffffu, m, o));
    if ((tid & 31) == 0) red[tid >> 5] = m;
    __syncthreads();
    float bm = red[0];
#pragma unroll
    for (int i = 1; i < 8; i++) bm = fmaxf(bm, red[i]);
    __syncthreads();

    float s = 0.f;
#pragma unroll
    for (int i = 0; i < 8; i++) {
        vals[i] = __expf(vals[i] - bm);
        s += vals[i];
    }
#pragma unroll
    for (int o = 16; o; o >>= 1) s += __shfl_xor_sync(0xffffffffu, s, o);
    if ((tid & 31) == 0) red[tid >> 5] = s;
    __syncthreads();
    float tot = 0.f;
#pragma unroll
    for (int i = 0; i < 8; i++) tot += red[i];
    float inv = 1.0f / tot;
#pragma unroll
    for (int i = 0; i < 8; i++)
        row[tid + i * 256] = vals[i] * inv;
}

// ---------------------------------------------------------------------------
// Stage 4: O = P * Vp per batch, written straight to d_out. grid: (4, 16, 8)
// ---------------------------------------------------------------------------
__global__ __launch_bounds__(256) void pv_kernel(float* __restrict__ out)
{
    gemm128<false, false>(g_S + (size_t)blockIdx.z * SEQ * SEQ,
                          g_Vp + (size_t)blockIdx.z * SEQ * CH,
                          out + (size_t)blockIdx.z * SEQ * CH,
                          nullptr, SEQ, CH, 1.0f);
}

// ---------------------------------------------------------------------------
extern "C" void kernel_launch(void* const* d_in, const int* in_sizes, int n_in,
                              void* d_out, int out_size)
{
    const float* q  = (const float*)d_in[0];
    const float* k  = (const float*)d_in[1];
    const float* v  = (const float*)d_in[2];
    const float* Wq = (const float*)d_in[3];
    const float* bq = (const float*)d_in[4];
    const float* Wk = (const float*)d_in[5];
    const float* bk = (const float*)d_in[6];
    const float* Wv = (const float*)d_in[7];
    const float* bv = (const float*)d_in[8];
    float* out = (float*)d_out;

    dim3 gProj(CH / 128, ROWS / 128, 3);       // (4, 128, 3)
    proj_kernel<<<gProj, 256>>>(q, k, v, Wq, bq, Wk, bk, Wv, bv);

    dim3 gQK(SEQ / 128, SEQ / 128, BATCH);     // (16, 16, 8)
    qk_kernel<<<gQK, 256>>>();

    softmax_kernel<<<ROWS, 256>>>();           // 16384 rows

    dim3 gPV(CH / 128, SEQ / 128, BATCH);      // (4, 16, 8)
    pv_kernel<<<gPV, 256>>>(out);
}

// round 3
// speedup vs baseline: 1.1927x; 1.1927x over previous
#include <cuda_runtime.h>
#include <cuda_bf16.h>
#include <cstdint>

#define BATCH 8
#define SEQ   2048
#define CH    512
#define ROWS  (BATCH * SEQ)   // 16384
#define SCALE 0.25f

// Scratch: projected Q/K/V (fp32) and attention scores S (fp32).
__device__ float g_Qp[(size_t)ROWS * CH];
__device__ float g_Kp[(size_t)ROWS * CH];
__device__ float g_Vp[(size_t)ROWS * CH];
__device__ float g_S[(size_t)BATCH * SEQ * SEQ];

// ---------------------------------------------------------------------------
// Helpers
// ---------------------------------------------------------------------------
__device__ __forceinline__ uint32_t smem_u32(const void* p) {
    uint32_t a;
    asm("{ .reg .u64 t; cvta.to.shared.u64 t, %1; cvt.u32.u64 %0, t; }"
        : "=r"(a) : "l"(p));
    return a;
}

#define LDMATRIX_X4(r0, r1, r2, r3, addr) \
    asm volatile("ldmatrix.sync.aligned.m8n8.x4.shared.b16 {%0,%1,%2,%3}, [%4];" \
                 : "=r"(r0), "=r"(r1), "=r"(r2), "=r"(r3) : "r"(addr))

__device__ __forceinline__ void mma_bf16(float* c,
                                         uint32_t a0, uint32_t a1, uint32_t a2, uint32_t a3,
                                         uint32_t b0, uint32_t b1) {
    asm volatile(
        "mma.sync.aligned.m16n8k16.row.col.f32.bf16.bf16.f32 "
        "{%0,%1,%2,%3}, {%4,%5,%6,%7}, {%8,%9}, {%0,%1,%2,%3};"
        : "+f"(c[0]), "+f"(c[1]), "+f"(c[2]), "+f"(c[3])
        : "r"(a0), "r"(a1), "r"(a2), "r"(a3), "r"(b0), "r"(b1));
}

// Split fp32 pair into packed bf16 hi / lo words.
__device__ __forceinline__ void split2(float x, float y, uint32_t& hi, uint32_t& lo) {
    __nv_bfloat16 hx = __float2bfloat16(x);
    __nv_bfloat16 hy = __float2bfloat16(y);
    __nv_bfloat16 lx = __float2bfloat16(x - __bfloat162float(hx));
    __nv_bfloat16 ly = __float2bfloat16(y - __bfloat162float(hy));
    __nv_bfloat162 H = __halves2bfloat162(hx, hy);
    __nv_bfloat162 L = __halves2bfloat162(lx, ly);
    hi = *reinterpret_cast<uint32_t*>(&H);
    lo = *reinterpret_cast<uint32_t*>(&L);
}

// ---------------------------------------------------------------------------
// Split-bf16 HMMA GEMM: one 128x128 tile of C = A[M,K] * B^T (+bias) (*alpha on A).
//   BTRANS=false: B source is [N_total, K] row-major (K-major rows, direct).
//   BTRANS=true : B source is [K_total, ldB]; B(n,k) = Bsrc[k*ldB + colBlock + n].
// 256 threads = 8 warps (4 row x 2 col), warp tile 32x64, BK=32.
// SMEM: hi/lo A and B as [128][40] bf16 (pad 40 -> conflict-free ldmatrix).
// ---------------------------------------------------------------------------
#define BK   32
#define LDA  40

template<bool BTRANS, bool HAS_BIAS>
__device__ __forceinline__ void tc_gemm(
    const float* __restrict__ A, const float* __restrict__ Bsrc,
    const float* __restrict__ bias, float* __restrict__ C,
    int K_total, int N_C, int ldB, float alpha)
{
    __shared__ __align__(16) __nv_bfloat16 sAhi[128 * LDA];
    __shared__ __align__(16) __nv_bfloat16 sAlo[128 * LDA];
    __shared__ __align__(16) __nv_bfloat16 sBhi[128 * LDA];
    __shared__ __align__(16) __nv_bfloat16 sBlo[128 * LDA];

    const int tid  = threadIdx.x;
    const int lane = tid & 31;
    const int wid  = tid >> 5;
    const int warpRow = wid & 3;     // 0..3 -> 32-row strip
    const int warpCol = wid >> 2;    // 0..1 -> 64-col strip
    const int rowBlock = blockIdx.y * 128;
    const int colBlock = blockIdx.x * 128;

    const uint32_t uAhi = smem_u32(sAhi);
    const uint32_t uAlo = smem_u32(sAlo);
    const uint32_t uBhi = smem_u32(sBhi);
    const uint32_t uBlo = smem_u32(sBlo);

    // ldmatrix lane-address components (element offsets into [128][LDA]).
    // A x4 (m16 x k16): rows lane&15, col half (lane>>4)*8.
    const int aLdRow = lane & 15;
    const int aLdCol = (lane >> 4) << 3;
    // B x4 (two n8 tiles x k16): n = (lane>>4)*8 + (lane&7), k half ((lane>>3)&1)*8.
    const int bLdRow = ((lane >> 4) << 3) + (lane & 7);
    const int bLdCol = ((lane >> 3) & 1) << 3;

    float acc[2][8][4];
#pragma unroll
    for (int mt = 0; mt < 2; mt++)
#pragma unroll
        for (int nt = 0; nt < 8; nt++)
#pragma unroll
            for (int e = 0; e < 4; e++) acc[mt][nt][e] = 0.f;

    const int ntiles = K_total / BK;
    float4 pa[4], pb[4];

    // Gmem load mappings.
    const int aRow = tid >> 1;                 // f>>3 with f=i*256+tid -> rows 0..127
    // (recomputed per i below for clarity)

    // ---- Prologue: load ktile 0 into registers ----
    {
        const float* Ab = A + (size_t)rowBlock * K_total;
#pragma unroll
        for (int i = 0; i < 4; i++) {
            int f = i * 256 + tid;
            int r = f >> 3, k4 = (f & 7) << 2;
            pa[i] = *(const float4*)(Ab + (size_t)r * K_total + k4);
        }
        if (!BTRANS) {
            const float* Bb = Bsrc + (size_t)colBlock * K_total;
#pragma unroll
            for (int i = 0; i < 4; i++) {
                int f = i * 256 + tid;
                int r = f >> 3, k4 = (f & 7) << 2;
                pb[i] = *(const float4*)(Bb + (size_t)r * K_total + k4);
            }
        } else {
            const float* Bb = Bsrc + colBlock;
#pragma unroll
            for (int i = 0; i < 4; i++) {
                int f = i * 256 + tid;
                int kk = f >> 5, n4 = (f & 31) << 2;
                pb[i] = *(const float4*)(Bb + (size_t)kk * ldB + n4);
            }
        }
    }

    for (int kt = 0; kt < ntiles; kt++) {
        // ---- Convert + store current tile to SMEM ----
#pragma unroll
        for (int i = 0; i < 4; i++) {
            int f = i * 256 + tid;
            int r = f >> 3, k4 = (f & 7) << 2;
            float4 v = pa[i];
            v.x *= alpha; v.y *= alpha; v.z *= alpha; v.w *= alpha;
            uint32_t h01, l01, h23, l23;
            split2(v.x, v.y, h01, l01);
            split2(v.z, v.w, h23, l23);
            *(uint2*)&sAhi[r * LDA + k4] = make_uint2(h01, h23);
            *(uint2*)&sAlo[r * LDA + k4] = make_uint2(l01, l23);
        }
        if (!BTRANS) {
#pragma unroll
            for (int i = 0; i < 4; i++) {
                int f = i * 256 + tid;
                int r = f >> 3, k4 = (f & 7) << 2;
                float4 v = pb[i];
                uint32_t h01, l01, h23, l23;
                split2(v.x, v.y, h01, l01);
                split2(v.z, v.w, h23, l23);
                *(uint2*)&sBhi[r * LDA + k4] = make_uint2(h01, h23);
                *(uint2*)&sBlo[r * LDA + k4] = make_uint2(l01, l23);
            }
        } else {
#pragma unroll
            for (int i = 0; i < 4; i++) {
                int f = i * 256 + tid;
                int kk = f >> 5, n4 = (f & 31) << 2;
                float vv[4] = {pb[i].x, pb[i].y, pb[i].z, pb[i].w};
#pragma unroll
                for (int j = 0; j < 4; j++) {
                    __nv_bfloat16 h = __float2bfloat16(vv[j]);
                    __nv_bfloat16 l = __float2bfloat16(vv[j] - __bfloat162float(h));
                    sBhi[(n4 + j) * LDA + kk] = h;
                    sBlo[(n4 + j) * LDA + kk] = l;
                }
            }
        }
        __syncthreads();

        // ---- Prefetch next ktile into registers (hidden under MMA) ----
        if (kt + 1 < ntiles) {
            const float* Ab = A + (size_t)rowBlock * K_total + (kt + 1) * BK;
#pragma unroll
            for (int i = 0; i < 4; i++) {
                int f = i * 256 + tid;
                int r = f >> 3, k4 = (f & 7) << 2;
                pa[i] = *(const float4*)(Ab + (size_t)r * K_total + k4);
            }
            if (!BTRANS) {
                const float* Bb = Bsrc + (size_t)colBlock * K_total + (kt + 1) * BK;
#pragma unroll
                for (int i = 0; i < 4; i++) {
                    int f = i * 256 + tid;
                    int r = f >> 3, k4 = (f & 7) << 2;
                    pb[i] = *(const float4*)(Bb + (size_t)r * K_total + k4);
                }
            } else {
                const float* Bb = Bsrc + (size_t)((kt + 1) * BK) * ldB + colBlock;
#pragma unroll
                for (int i = 0; i < 4; i++) {
                    int f = i * 256 + tid;
                    int kk = f >> 5, n4 = (f & 31) << 2;
                    pb[i] = *(const float4*)(Bb + (size_t)kk * ldB + n4);
                }
            }
        }

        // ---- MMA over the SMEM tile: 2 k-steps of 16 ----
#pragma unroll
        for (int ks = 0; ks < 2; ks++) {
            const int kb = ks * 16;
            uint32_t ah[2][4], al[2][4];
#pragma unroll
            for (int mt = 0; mt < 2; mt++) {
                int r = warpRow * 32 + mt * 16 + aLdRow;
                uint32_t off = (uint32_t)(r * LDA + kb + aLdCol) * 2;
                LDMATRIX_X4(ah[mt][0], ah[mt][1], ah[mt][2], ah[mt][3], uAhi + off);
                LDMATRIX_X4(al[mt][0], al[mt][1], al[mt][2], al[mt][3], uAlo + off);
            }
#pragma unroll
            for (int np = 0; np < 4; np++) {
                int n = warpCol * 64 + np * 16 + bLdRow;
                uint32_t off = (uint32_t)(n * LDA + kb + bLdCol) * 2;
                uint32_t bh[4], bl[4];
                LDMATRIX_X4(bh[0], bh[1], bh[2], bh[3], uBhi + off);
                LDMATRIX_X4(bl[0], bl[1], bl[2], bl[3], uBlo + off);
#pragma unroll
                for (int mt = 0; mt < 2; mt++) {
#pragma unroll
                    for (int half = 0; half < 2; half++) {
                        int nt = np * 2 + half;
                        uint32_t bh0 = bh[half * 2], bh1 = bh[half * 2 + 1];
                        uint32_t bl0 = bl[half * 2], bl1 = bl[half * 2 + 1];
                        mma_bf16(acc[mt][nt], ah[mt][0], ah[mt][1], ah[mt][2], ah[mt][3], bh0, bh1);
                        mma_bf16(acc[mt][nt], ah[mt][0], ah[mt][1], ah[mt][2], ah[mt][3], bl0, bl1);
                        mma_bf16(acc[mt][nt], al[mt][0], al[mt][1], al[mt][2], al[mt][3], bh0, bh1);
                    }
                }
            }
        }
        __syncthreads();
    }

    // ---- Epilogue ----
#pragma unroll
    for (int mt = 0; mt < 2; mt++) {
#pragma unroll
        for (int nt = 0; nt < 8; nt++) {
            int row = rowBlock + warpRow * 32 + mt * 16 + (lane >> 2);
            int col = colBlock + warpCol * 64 + nt * 8 + (lane & 3) * 2;
            float2 lo = make_float2(acc[mt][nt][0], acc[mt][nt][1]);
            float2 hi = make_float2(acc[mt][nt][2], acc[mt][nt][3]);
            if (HAS_BIAS) {
                float2 b = *(const float2*)(bias + col);
                lo.x += b.x; lo.y += b.y;
                hi.x += b.x; hi.y += b.y;
            }
            *(float2*)(C + (size_t)row * N_C + col)       = lo;
            *(float2*)(C + (size_t)(row + 8) * N_C + col) = hi;
        }
    }
}

// ---------------------------------------------------------------------------
// Stage 1: fused Q/K/V projections. grid (4, 128, 3). C = X*W + b (W transposed on load).
// ---------------------------------------------------------------------------
__global__ __launch_bounds__(256, 1) void proj_kernel(
    const float* __restrict__ q, const float* __restrict__ k, const float* __restrict__ v,
    const float* __restrict__ Wq, const float* __restrict__ bq,
    const float* __restrict__ Wk, const float* __restrict__ bk,
    const float* __restrict__ Wv, const float* __restrict__ bv)
{
    const float *A, *W, *bias; float* C;
    if (blockIdx.z == 0)      { A = q; W = Wq; bias = bq; C = g_Qp; }
    else if (blockIdx.z == 1) { A = k; W = Wk; bias = bk; C = g_Kp; }
    else                      { A = v; W = Wv; bias = bv; C = g_Vp; }
    tc_gemm<true, true>(A, W, bias, C, CH, CH, CH, 1.0f);
}

// ---------------------------------------------------------------------------
// Stage 2: S = (SCALE*Qp) * Kp^T per batch. grid (16, 16, 8).
// ---------------------------------------------------------------------------
__global__ __launch_bounds__(256, 1) void qk_kernel()
{
    size_t boff = (size_t)blockIdx.z * SEQ * CH;
    tc_gemm<false, false>(g_Qp + boff, g_Kp + boff, nullptr,
                          g_S + (size_t)blockIdx.z * SEQ * SEQ,
                          CH, SEQ, CH, SCALE);
}

// ---------------------------------------------------------------------------
// Stage 3: row softmax over S, in place. grid 16384 x 256.
// ---------------------------------------------------------------------------
__global__ __launch_bounds__(256) void softmax_kernel()
{
    __shared__ float red[8];
    float* row = g_S + (size_t)blockIdx.x * SEQ;
    const int tid = threadIdx.x;

    float vals[8];
    float m = -3.0e38f;
#pragma unroll
    for (int i = 0; i < 8; i++) {
        vals[i] = row[tid + i * 256];
        m = fmaxf(m, vals[i]);
    }
#pragma unroll
    for (int o = 16; o; o >>= 1) m = fmaxf(m, __shfl_xor_sync(0xffffffffu, m, o));
    if ((tid & 31) == 0) red[tid >> 5] = m;
    __syncthreads();
    float bm = red[0];
#pragma unroll
    for (int i = 1; i < 8; i++) bm = fmaxf(bm, red[i]);
    __syncthreads();

    float s = 0.f;
#pragma unroll
    for (int i = 0; i < 8; i++) {
        vals[i] = __expf(vals[i] - bm);
        s += vals[i];
    }
#pragma unroll
    for (int o = 16; o; o >>= 1) s += __shfl_xor_sync(0xffffffffu, s, o);
    if ((tid & 31) == 0) red[tid >> 5] = s;
    __syncthreads();
    float tot = 0.f;
#pragma unroll
    for (int i = 0; i < 8; i++) tot += red[i];
    float inv = 1.0f / tot;
#pragma unroll
    for (int i = 0; i < 8; i++)
        row[tid + i * 256] = vals[i] * inv;
}

// ---------------------------------------------------------------------------
// Stage 4: O = P * Vp per batch (V transposed on load). grid (4, 16, 8).
// ---------------------------------------------------------------------------
__global__ __launch_bounds__(256, 1) void pv_kernel(float* __restrict__ out)
{
    tc_gemm<true, false>(g_S + (size_t)blockIdx.z * SEQ * SEQ,
                         g_Vp + (size_t)blockIdx.z * SEQ * CH, nullptr,
                         out + (size_t)blockIdx.z * SEQ * CH,
                         SEQ, CH, CH, 1.0f);
}

// ---------------------------------------------------------------------------
extern "C" void kernel_launch(void* const* d_in, const int* in_sizes, int n_in,
                              void* d_out, int out_size)
{
    const float* q  = (const float*)d_in[0];
    const float* k  = (const float*)d_in[1];
    const float* v  = (const float*)d_in[2];
    const float* Wq = (const float*)d_in[3];
    const float* bq = (const float*)d_in[4];
    const float* Wk = (const float*)d_in[5];
    const float* bk = (const float*)d_in[6];
    const float* Wv = (const float*)d_in[7];
    const float* bv = (const float*)d_in[8];
    float* out = (float*)d_out;

    dim3 gProj(CH / 128, ROWS / 128, 3);      // (4, 128, 3)
    proj_kernel<<<gProj, 256>>>(q, k, v, Wq, bq, Wk, bk, Wv, bv);

    dim3 gQK(SEQ / 128, SEQ / 128, BATCH);    // (16, 16, 8)
    qk_kernel<<<gQK, 256>>>();

    softmax_kernel<<<ROWS, 256>>>();          // 16384 rows

    dim3 gPV(CH / 128, SEQ / 128, BATCH);     // (4, 16, 8)
    pv_kernel<<<gPV, 256>>>(out);
}

// round 4
// speedup vs baseline: 2.5183x; 2.1114x over previous
#include <cuda_runtime.h>
#include <cuda_bf16.h>
#include <cstdint>

#define BATCH 8
#define SEQ   2048
#define CH    512
#define ROWS  (BATCH * SEQ)          // 16384
#define SCALE 0.25f
#define RC    ((size_t)ROWS * CH)    // 8388608
#define SS    ((size_t)BATCH * SEQ * SEQ)

// ---------------- persistent scratch (module-static, allowed) ----------------
__device__ __nv_bfloat16 g_Ihi[3 * RC], g_Ilo[3 * RC];          // split inputs q,k,v
__device__ __nv_bfloat16 g_Whi[3 * CH * CH], g_Wlo[3 * CH * CH];// split weights
__device__ __nv_bfloat16 g_Qhi[RC], g_Qlo[RC];                  // proj outputs (Q pre-scaled)
__device__ __nv_bfloat16 g_Khi[RC], g_Klo[RC];
__device__ __nv_bfloat16 g_Vhi[RC], g_Vlo[RC];
__device__ float         g_S[SS];                               // raw scores
__device__ __nv_bfloat16 g_Shi[SS], g_Slo[SS];                  // split softmax probs

// ---------------- smem layout: 2 stages x (Ahi,Alo,Bhi,Blo) ----------------
#define LDA         40        // A smem pitch, elems (80 B rows)
#define LDBT        136       // trans-B smem pitch, elems (272 B rows)
#define MAT_BYTES   10240
#define OFF_AHI     0
#define OFF_ALO     10240
#define OFF_BHI     20480
#define OFF_BLO     30720
#define STAGE_BYTES 40960
#define SMEM_TOTAL  (2 * STAGE_BYTES)

extern __shared__ char dsmem[];

// ---------------- PTX helpers ----------------
__device__ __forceinline__ uint32_t smem_u32(const void* p) {
    uint32_t a;
    asm("{ .reg .u64 t; cvta.to.shared.u64 t, %1; cvt.u32.u64 %0, t; }"
        : "=r"(a) : "l"(p));
    return a;
}
__device__ __forceinline__ void cp16(uint32_t dst, const void* src) {
    asm volatile("cp.async.cg.shared.global [%0], [%1], 16;" :: "r"(dst), "l"(src));
}
#define CP_COMMIT() asm volatile("cp.async.commit_group;" ::: "memory")
#define CP_WAIT0()  asm volatile("cp.async.wait_group 0;" ::: "memory")
#define CP_WAIT1()  asm volatile("cp.async.wait_group 1;" ::: "memory")

#define LDMATRIX_X4(r0, r1, r2, r3, addr) \
    asm volatile("ldmatrix.sync.aligned.m8n8.x4.shared.b16 {%0,%1,%2,%3}, [%4];" \
                 : "=r"(r0), "=r"(r1), "=r"(r2), "=r"(r3) : "r"(addr))
#define LDMATRIX_X4_T(r0, r1, r2, r3, addr) \
    asm volatile("ldmatrix.sync.aligned.m8n8.x4.trans.shared.b16 {%0,%1,%2,%3}, [%4];" \
                 : "=r"(r0), "=r"(r1), "=r"(r2), "=r"(r3) : "r"(addr))

__device__ __forceinline__ void mma_bf16(float* c,
                                         uint32_t a0, uint32_t a1, uint32_t a2, uint32_t a3,
                                         uint32_t b0, uint32_t b1) {
    asm volatile(
        "mma.sync.aligned.m16n8k16.row.col.f32.bf16.bf16.f32 "
        "{%0,%1,%2,%3}, {%4,%5,%6,%7}, {%8,%9}, {%0,%1,%2,%3};"
        : "+f"(c[0]), "+f"(c[1]), "+f"(c[2]), "+f"(c[3])
        : "r"(a0), "r"(a1), "r"(a2), "r"(a3), "r"(b0), "r"(b1));
}

__device__ __forceinline__ void split2(float x, float y, uint32_t& hi, uint32_t& lo) {
    __nv_bfloat16 hx = __float2bfloat16(x);
    __nv_bfloat16 hy = __float2bfloat16(y);
    __nv_bfloat16 lx = __float2bfloat16(x - __bfloat162float(hx));
    __nv_bfloat16 ly = __float2bfloat16(y - __bfloat162float(hy));
    __nv_bfloat162 H = __halves2bfloat162(hx, hy);
    __nv_bfloat162 L = __halves2bfloat162(lx, ly);
    hi = *reinterpret_cast<uint32_t*>(&H);
    lo = *reinterpret_cast<uint32_t*>(&L);
}

// ---------------- tile loaders (cp.async) ----------------
__device__ __forceinline__ void ld_tileA(
    uint32_t sb, const __nv_bfloat16* Ahi, const __nv_bfloat16* Alo,
    int ldA, int rowBlock, int k0, int tid)
{
#pragma unroll
    for (int i = 0; i < 2; i++) {
        int c = i * 256 + tid;            // 512 chunks: 128 rows x 4
        int r = c >> 2, j = c & 3;
        size_t g = (size_t)(rowBlock + r) * ldA + k0 + j * 8;
        uint32_t d = r * 80 + j * 16;
        cp16(sb + OFF_AHI + d, Ahi + g);
        cp16(sb + OFF_ALO + d, Alo + g);
    }
}
// B K-major [n][k] source (non-trans ldmatrix)
__device__ __forceinline__ void ld_tileB_k(
    uint32_t sb, const __nv_bfloat16* Bhi, const __nv_bfloat16* Blo,
    int ldB, int colBlock, int k0, int tid)
{
#pragma unroll
    for (int i = 0; i < 2; i++) {
        int c = i * 256 + tid;
        int r = c >> 2, j = c & 3;
        size_t g = (size_t)(colBlock + r) * ldB + k0 + j * 8;
        uint32_t d = r * 80 + j * 16;
        cp16(sb + OFF_BHI + d, Bhi + g);
        cp16(sb + OFF_BLO + d, Blo + g);
    }
}
// B MN-major [k][n] source (trans ldmatrix): smem [32][136]
__device__ __forceinline__ void ld_tileB_t(
    uint32_t sb, const __nv_bfloat16* Bhi, const __nv_bfloat16* Blo,
    int ldB, int colBlock, int k0, int tid)
{
#pragma unroll
    for (int i = 0; i < 2; i++) {
        int c = i * 256 + tid;            // 512 chunks: 32 rows x 16
        int k = c >> 4, j = c & 15;
        size_t g = (size_t)(k0 + k) * ldB + colBlock + j * 8;
        uint32_t d = k * 272 + j * 16;
        cp16(sb + OFF_BHI + d, Bhi + g);
        cp16(sb + OFF_BLO + d, Blo + g);
    }
}

// ---------------- GEMM core: 128x128 tile, BK=32, 3-term split ----------------
// BT=false: B from [n][k]; BT=true: B from [k][n] via ldmatrix.trans.
template<bool BT>
__device__ __forceinline__ void tc_core(
    const __nv_bfloat16* __restrict__ Ahi, const __nv_bfloat16* __restrict__ Alo,
    const __nv_bfloat16* __restrict__ Bhi, const __nv_bfloat16* __restrict__ Blo,
    int K_total, int ldB, int rowBlock, int colBlock,
    float acc[2][8][4])
{
    const int tid  = threadIdx.x;
    const int lane = tid & 31;
    const int wid  = tid >> 5;
    const int warpRow = wid & 3;
    const int warpCol = wid >> 2;

    const uint32_t sbase = smem_u32(dsmem);

#pragma unroll
    for (int mt = 0; mt < 2; mt++)
#pragma unroll
        for (int nt = 0; nt < 8; nt++)
#pragma unroll
            for (int e = 0; e < 4; e++) acc[mt][nt][e] = 0.f;

    // ldmatrix per-thread byte offsets
    const uint32_t aOff = ((warpRow * 32 + (lane & 15)) * LDA + ((lane >> 4) << 3)) * 2;
    const uint32_t bOffK = ((warpCol * 64 + ((lane >> 4) << 3) + (lane & 7)) * LDA
                           + (((lane >> 3) & 1) << 3)) * 2;
    const uint32_t bOffT = ((lane & 15) * LDBT + warpCol * 64 + ((lane >> 4) << 3)) * 2;

    const int ntiles = K_total >> 5;

    // prologue: stages 0,1
    ld_tileA(sbase, Ahi, Alo, K_total, rowBlock, 0, tid);
    if (BT) ld_tileB_t(sbase, Bhi, Blo, ldB, colBlock, 0, tid);
    else    ld_tileB_k(sbase, Bhi, Blo, ldB, colBlock, 0, tid);
    CP_COMMIT();
    ld_tileA(sbase + STAGE_BYTES, Ahi, Alo, K_total, rowBlock, 32, tid);
    if (BT) ld_tileB_t(sbase + STAGE_BYTES, Bhi, Blo, ldB, colBlock, 32, tid);
    else    ld_tileB_k(sbase + STAGE_BYTES, Bhi, Blo, ldB, colBlock, 32, tid);
    CP_COMMIT();

    for (int kt = 0; kt < ntiles; kt++) {
        if (kt + 1 < ntiles) { CP_WAIT1(); } else { CP_WAIT0(); }
        __syncthreads();

        const uint32_t sb = sbase + (kt & 1) * STAGE_BYTES;
#pragma unroll
        for (int ks = 0; ks < 2; ks++) {
            const int kb = ks * 16;
            uint32_t ah[2][4], al[2][4];
#pragma unroll
            for (int mt = 0; mt < 2; mt++) {
                uint32_t ad = sb + aOff + (mt * 16 * LDA + kb) * 2;
                LDMATRIX_X4(ah[mt][0], ah[mt][1], ah[mt][2], ah[mt][3], ad + OFF_AHI);
                LDMATRIX_X4(al[mt][0], al[mt][1], al[mt][2], al[mt][3], ad + OFF_ALO);
            }
#pragma unroll
            for (int np = 0; np < 4; np++) {
                uint32_t bh[4], bl[4];
                if (BT) {
                    uint32_t bd = sb + bOffT + (kb * LDBT + np * 16) * 2;
                    LDMATRIX_X4_T(bh[0], bh[1], bh[2], bh[3], bd + OFF_BHI);
                    LDMATRIX_X4_T(bl[0], bl[1], bl[2], bl[3], bd + OFF_BLO);
                } else {
                    uint32_t bd = sb + bOffK + (np * 16 * LDA + kb) * 2;
                    LDMATRIX_X4(bh[0], bh[1], bh[2], bh[3], bd + OFF_BHI);
                    LDMATRIX_X4(bl[0], bl[1], bl[2], bl[3], bd + OFF_BLO);
                }
#pragma unroll
                for (int half = 0; half < 2; half++) {
                    uint32_t bh0 = bh[half * 2], bh1 = bh[half * 2 + 1];
                    uint32_t bl0 = bl[half * 2], bl1 = bl[half * 2 + 1];
#pragma unroll
                    for (int mt = 0; mt < 2; mt++) {
                        int nt = np * 2 + half;
                        mma_bf16(acc[mt][nt], ah[mt][0], ah[mt][1], ah[mt][2], ah[mt][3], bh0, bh1);
                        mma_bf16(acc[mt][nt], ah[mt][0], ah[mt][1], ah[mt][2], ah[mt][3], bl0, bl1);
                        mma_bf16(acc[mt][nt], al[mt][0], al[mt][1], al[mt][2], al[mt][3], bh0, bh1);
                    }
                }
            }
        }
        __syncthreads();

        if (kt + 2 < ntiles) {
            const uint32_t sb2 = sbase + (kt & 1) * STAGE_BYTES;
            const int k0 = (kt + 2) * 32;
            ld_tileA(sb2, Ahi, Alo, K_total, rowBlock, k0, tid);
            if (BT) ld_tileB_t(sb2, Bhi, Blo, ldB, colBlock, k0, tid);
            else    ld_tileB_k(sb2, Bhi, Blo, ldB, colBlock, k0, tid);
            CP_COMMIT();
        }
    }
}

// ---------------- Stage 0: split inputs + weights to bf16 hi/lo ----------------
__global__ __launch_bounds__(256) void pre_kernel(
    const float* __restrict__ q, const float* __restrict__ k, const float* __restrict__ v,
    const float* __restrict__ Wq, const float* __restrict__ Wk, const float* __restrict__ Wv)
{
    const int z = blockIdx.z;
    const float* src;
    __nv_bfloat16 *hi, *lo;
    size_t n4;
    if (z < 3) {
        src = (z == 0) ? q : (z == 1) ? k : v;
        hi = g_Ihi + (size_t)z * RC; lo = g_Ilo + (size_t)z * RC;
        n4 = RC / 4;
    } else {
        int w = z - 3;
        src = (w == 0) ? Wq : (w == 1) ? Wk : Wv;
        hi = g_Whi + (size_t)w * CH * CH; lo = g_Wlo + (size_t)w * CH * CH;
        n4 = (size_t)CH * CH / 4;
    }
    size_t i4 = (size_t)blockIdx.x * 256 + threadIdx.x;
    if (i4 >= n4) return;
    float4 val = ((const float4*)src)[i4];
    uint32_t h01, l01, h23, l23;
    split2(val.x, val.y, h01, l01);
    split2(val.z, val.w, h23, l23);
    *(uint2*)(hi + i4 * 4) = make_uint2(h01, h23);
    *(uint2*)(lo + i4 * 4) = make_uint2(l01, l23);
}

// ---------------- Stage 1: projections (output split bf16; Q pre-scaled) -------
__global__ __launch_bounds__(256, 2) void proj_kernel(
    const float* __restrict__ bq, const float* __restrict__ bk, const float* __restrict__ bv)
{
    const int z = blockIdx.z;
    const __nv_bfloat16* Ahi = g_Ihi + (size_t)z * RC;
    const __nv_bfloat16* Alo = g_Ilo + (size_t)z * RC;
    const __nv_bfloat16* Bhi = g_Whi + (size_t)z * CH * CH;
    const __nv_bfloat16* Blo = g_Wlo + (size_t)z * CH * CH;
    const float* bias = (z == 0) ? bq : (z == 1) ? bk : bv;
    __nv_bfloat16* Chi = (z == 0) ? g_Qhi : (z == 1) ? g_Khi : g_Vhi;
    __nv_bfloat16* Clo = (z == 0) ? g_Qlo : (z == 1) ? g_Klo : g_Vlo;
    const float alpha = (z == 0) ? SCALE : 1.0f;

    const int rowBlock = blockIdx.y * 128;
    const int colBlock = blockIdx.x * 128;

    float acc[2][8][4];
    tc_core<true>(Ahi, Alo, Bhi, Blo, CH, CH, rowBlock, colBlock, acc);

    const int lane = threadIdx.x & 31;
    const int wid  = threadIdx.x >> 5;
    const int warpRow = wid & 3, warpCol = wid >> 2;
#pragma unroll
    for (int mt = 0; mt < 2; mt++) {
#pragma unroll
        for (int nt = 0; nt < 8; nt++) {
            int row = rowBlock + warpRow * 32 + mt * 16 + (lane >> 2);
            int col = colBlock + warpCol * 64 + nt * 8 + (lane & 3) * 2;
            float2 b = *(const float2*)(bias + col);
            float x0 = (acc[mt][nt][0] + b.x) * alpha;
            float y0 = (acc[mt][nt][1] + b.y) * alpha;
            float x1 = (acc[mt][nt][2] + b.x) * alpha;
            float y1 = (acc[mt][nt][3] + b.y) * alpha;
            uint32_t h, l;
            split2(x0, y0, h, l);
            *(uint32_t*)(Chi + (size_t)row * CH + col) = h;
            *(uint32_t*)(Clo + (size_t)row * CH + col) = l;
            split2(x1, y1, h, l);
            *(uint32_t*)(Chi + (size_t)(row + 8) * CH + col) = h;
            *(uint32_t*)(Clo + (size_t)(row + 8) * CH + col) = l;
        }
    }
}

// ---------------- Stage 2: S = Q * K^T (scale already folded into Q) ----------
__global__ __launch_bounds__(256, 2) void qk_kernel()
{
    const int z = blockIdx.z;
    const size_t po = (size_t)z * SEQ * CH;
    float* S = g_S + (size_t)z * SEQ * SEQ;
    const int rowBlock = blockIdx.y * 128;
    const int colBlock = blockIdx.x * 128;

    float acc[2][8][4];
    tc_core<false>(g_Qhi + po, g_Qlo + po, g_Khi + po, g_Klo + po,
                   CH, CH, rowBlock, colBlock, acc);

    const int lane = threadIdx.x & 31;
    const int wid  = threadIdx.x >> 5;
    const int warpRow = wid & 3, warpCol = wid >> 2;
#pragma unroll
    for (int mt = 0; mt < 2; mt++) {
#pragma unroll
        for (int nt = 0; nt < 8; nt++) {
            int row = rowBlock + warpRow * 32 + mt * 16 + (lane >> 2);
            int col = colBlock + warpCol * 64 + nt * 8 + (lane & 3) * 2;
            *(float2*)(S + (size_t)row * SEQ + col) =
                make_float2(acc[mt][nt][0], acc[mt][nt][1]);
            *(float2*)(S + (size_t)(row + 8) * SEQ + col) =
                make_float2(acc[mt][nt][2], acc[mt][nt][3]);
        }
    }
}

// ---------------- Stage 3: softmax -> split bf16 probs ----------------
__global__ __launch_bounds__(256) void softmax_kernel()
{
    __shared__ float red[8];
    const size_t ro = (size_t)blockIdx.x * SEQ;
    const float* row = g_S + ro;
    const int tid = threadIdx.x;

    float vals[8];
    float m = -3.0e38f;
#pragma unroll
    for (int i = 0; i < 8; i++) {
        vals[i] = row[tid + i * 256];
        m = fmaxf(m, vals[i]);
    }
#pragma unroll
    for (int o = 16; o; o >>= 1) m = fmaxf(m, __shfl_xor_sync(0xffffffffu, m, o));
    if ((tid & 31) == 0) red[tid >> 5] = m;
    __syncthreads();
    float bm = red[0];
#pragma unroll
    for (int i = 1; i < 8; i++) bm = fmaxf(bm, red[i]);
    __syncthreads();

    float s = 0.f;
#pragma unroll
    for (int i = 0; i < 8; i++) {
        vals[i] = __expf(vals[i] - bm);
        s += vals[i];
    }
#pragma unroll
    for (int o = 16; o; o >>= 1) s += __shfl_xor_sync(0xffffffffu, s, o);
    if ((tid & 31) == 0) red[tid >> 5] = s;
    __syncthreads();
    float tot = 0.f;
#pragma unroll
    for (int i = 0; i < 8; i++) tot += red[i];
    float inv = 1.0f / tot;
#pragma unroll
    for (int i = 0; i < 8; i++) {
        float p = vals[i] * inv;
        __nv_bfloat16 h = __float2bfloat16(p);
        __nv_bfloat16 l = __float2bfloat16(p - __bfloat162float(h));
        g_Shi[ro + tid + i * 256] = h;
        g_Slo[ro + tid + i * 256] = l;
    }
}

// ---------------- Stage 4: O = P * V ----------------
__global__ __launch_bounds__(256, 2) void pv_kernel(float* __restrict__ out)
{
    const int z = blockIdx.z;
    const size_t so = (size_t)z * SEQ * SEQ;
    const size_t vo = (size_t)z * SEQ * CH;
    const int rowBlock = blockIdx.y * 128;
    const int colBlock = blockIdx.x * 128;

    float acc[2][8][4];
    tc_core<true>(g_Shi + so, g_Slo + so, g_Vhi + vo, g_Vlo + vo,
                  SEQ, CH, rowBlock, colBlock, acc);

    float* O = out + vo;
    const int lane = threadIdx.x & 31;
    const int wid  = threadIdx.x >> 5;
    const int warpRow = wid & 3, warpCol = wid >> 2;
#pragma unroll
    for (int mt = 0; mt < 2; mt++) {
#pragma unroll
        for (int nt = 0; nt < 8; nt++) {
            int row = rowBlock + warpRow * 32 + mt * 16 + (lane >> 2);
            int col = colBlock + warpCol * 64 + nt * 8 + (lane & 3) * 2;
            *(float2*)(O + (size_t)row * CH + col) =
                make_float2(acc[mt][nt][0], acc[mt][nt][1]);
            *(float2*)(O + (size_t)(row + 8) * CH + col) =
                make_float2(acc[mt][nt][2], acc[mt][nt][3]);
        }
    }
}

// ---------------------------------------------------------------------------
extern "C" void kernel_launch(void* const* d_in, const int* in_sizes, int n_in,
                              void* d_out, int out_size)
{
    const float* q  = (const float*)d_in[0];
    const float* k  = (const float*)d_in[1];
    const float* v  = (const float*)d_in[2];
    const float* Wq = (const float*)d_in[3];
    const float* bq = (const float*)d_in[4];
    const float* Wk = (const float*)d_in[5];
    const float* bk = (const float*)d_in[6];
    const float* Wv = (const float*)d_in[7];
    const float* bv = (const float*)d_in[8];
    float* out = (float*)d_out;

    static int configured = 0;
    if (!configured) {
        cudaFuncSetAttribute(proj_kernel, cudaFuncAttributeMaxDynamicSharedMemorySize, SMEM_TOTAL);
        cudaFuncSetAttribute(qk_kernel,   cudaFuncAttributeMaxDynamicSharedMemorySize, SMEM_TOTAL);
        cudaFuncSetAttribute(pv_kernel,   cudaFuncAttributeMaxDynamicSharedMemorySize, SMEM_TOTAL);
        configured = 1;
    }

    dim3 gPre(8192, 1, 6);
    pre_kernel<<<gPre, 256>>>(q, k, v, Wq, Wk, Wv);

    dim3 gProj(CH / 128, ROWS / 128, 3);      // (4, 128, 3)
    proj_kernel<<<gProj, 256, SMEM_TOTAL>>>(bq, bk, bv);

    dim3 gQK(SEQ / 128, SEQ / 128, BATCH);    // (16, 16, 8)
    qk_kernel<<<gQK, 256, SMEM_TOTAL>>>();

    softmax_kernel<<<ROWS, 256>>>();          // 16384 rows

    dim3 gPV(CH / 128, SEQ / 128, BATCH);     // (4, 16, 8)
    pv_kernel<<<gPV, 256, SMEM_TOTAL>>>(out);
}

// round 5
// speedup vs baseline: 2.5507x; 1.0128x over previous
#include <cuda_runtime.h>
#include <cuda_bf16.h>
#include <cstdint>

#define BATCH 8
#define SEQ   2048
#define CH    512
#define ROWS  (BATCH * SEQ)          // 16384
#define SCALE 0.25f
#define RC    ((size_t)ROWS * CH)    // 8388608
#define SS    ((size_t)BATCH * SEQ * SEQ)

// ---------------- persistent scratch (module-static, allowed) ----------------
__device__ __nv_bfloat16 g_Ihi[3 * RC], g_Ilo[3 * RC];          // split inputs q,k,v
__device__ __nv_bfloat16 g_Whi[3 * CH * CH], g_Wlo[3 * CH * CH];// split weights
__device__ __nv_bfloat16 g_Qhi[RC], g_Qlo[RC];                  // proj outputs (Q pre-scaled)
__device__ __nv_bfloat16 g_Khi[RC], g_Klo[RC];
__device__ __nv_bfloat16 g_Vhi[RC], g_Vlo[RC];
__device__ float         g_S[SS];                               // raw scores
__device__ __nv_bfloat16 g_Shi[SS], g_Slo[SS];                  // split softmax probs

// ---------------- smem layout: 2 stages x (Ahi,Alo,Bhi,Blo) ----------------
#define LDA         40        // A smem pitch, elems (80 B rows)
#define LDBT        136       // trans-B smem pitch, elems (272 B rows)
#define MAT_BYTES   10240
#define OFF_AHI     0
#define OFF_ALO     10240
#define OFF_BHI     20480
#define OFF_BLO     30720
#define STAGE_BYTES 40960
#define SMEM_TOTAL  (2 * STAGE_BYTES)

extern __shared__ char dsmem[];

// ---------------- PTX helpers ----------------
__device__ __forceinline__ uint32_t smem_u32(const void* p) {
    uint32_t a;
    asm("{ .reg .u64 t; cvta.to.shared.u64 t, %1; cvt.u32.u64 %0, t; }"
        : "=r"(a) : "l"(p));
    return a;
}
__device__ __forceinline__ void cp16(uint32_t dst, const void* src) {
    asm volatile("cp.async.cg.shared.global [%0], [%1], 16;" :: "r"(dst), "l"(src));
}
#define CP_COMMIT() asm volatile("cp.async.commit_group;" ::: "memory")
#define CP_WAIT0()  asm volatile("cp.async.wait_group 0;" ::: "memory")
#define CP_WAIT1()  asm volatile("cp.async.wait_group 1;" ::: "memory")

#define LDMATRIX_X4(r0, r1, r2, r3, addr) \
    asm volatile("ldmatrix.sync.aligned.m8n8.x4.shared.b16 {%0,%1,%2,%3}, [%4];" \
                 : "=r"(r0), "=r"(r1), "=r"(r2), "=r"(r3) : "r"(addr))
#define LDMATRIX_X4_T(r0, r1, r2, r3, addr) \
    asm volatile("ldmatrix.sync.aligned.m8n8.x4.trans.shared.b16 {%0,%1,%2,%3}, [%4];" \
                 : "=r"(r0), "=r"(r1), "=r"(r2), "=r"(r3) : "r"(addr))

__device__ __forceinline__ void mma_bf16(float* c,
                                         uint32_t a0, uint32_t a1, uint32_t a2, uint32_t a3,
                                         uint32_t b0, uint32_t b1) {
    asm volatile(
        "mma.sync.aligned.m16n8k16.row.col.f32.bf16.bf16.f32 "
        "{%0,%1,%2,%3}, {%4,%5,%6,%7}, {%8,%9}, {%0,%1,%2,%3};"
        : "+f"(c[0]), "+f"(c[1]), "+f"(c[2]), "+f"(c[3])
        : "r"(a0), "r"(a1), "r"(a2), "r"(a3), "r"(b0), "r"(b1));
}

__device__ __forceinline__ void split2(float x, float y, uint32_t& hi, uint32_t& lo) {
    __nv_bfloat16 hx = __float2bfloat16(x);
    __nv_bfloat16 hy = __float2bfloat16(y);
    __nv_bfloat16 lx = __float2bfloat16(x - __bfloat162float(hx));
    __nv_bfloat16 ly = __float2bfloat16(y - __bfloat162float(hy));
    __nv_bfloat162 H = __halves2bfloat162(hx, hy);
    __nv_bfloat162 L = __halves2bfloat162(lx, ly);
    hi = *reinterpret_cast<uint32_t*>(&H);
    lo = *reinterpret_cast<uint32_t*>(&L);
}

// ---------------- tile loaders (cp.async) ----------------
__device__ __forceinline__ void ld_tileA(
    uint32_t sb, const __nv_bfloat16* Ahi, const __nv_bfloat16* Alo,
    int ldA, int rowBlock, int k0, int tid)
{
#pragma unroll
    for (int i = 0; i < 2; i++) {
        int c = i * 256 + tid;            // 512 chunks: 128 rows x 4
        int r = c >> 2, j = c & 3;
        size_t g = (size_t)(rowBlock + r) * ldA + k0 + j * 8;
        uint32_t d = r * 80 + j * 16;
        cp16(sb + OFF_AHI + d, Ahi + g);
        cp16(sb + OFF_ALO + d, Alo + g);
    }
}
// B K-major [n][k] source (non-trans ldmatrix)
__device__ __forceinline__ void ld_tileB_k(
    uint32_t sb, const __nv_bfloat16* Bhi, const __nv_bfloat16* Blo,
    int ldB, int colBlock, int k0, int tid)
{
#pragma unroll
    for (int i = 0; i < 2; i++) {
        int c = i * 256 + tid;
        int r = c >> 2, j = c & 3;
        size_t g = (size_t)(colBlock + r) * ldB + k0 + j * 8;
        uint32_t d = r * 80 + j * 16;
        cp16(sb + OFF_BHI + d, Bhi + g);
        cp16(sb + OFF_BLO + d, Blo + g);
    }
}
// B MN-major [k][n] source (trans ldmatrix): smem [32][136]
__device__ __forceinline__ void ld_tileB_t(
    uint32_t sb, const __nv_bfloat16* Bhi, const __nv_bfloat16* Blo,
    int ldB, int colBlock, int k0, int tid)
{
#pragma unroll
    for (int i = 0; i < 2; i++) {
        int c = i * 256 + tid;            // 512 chunks: 32 rows x 16
        int k = c >> 4, j = c & 15;
        size_t g = (size_t)(k0 + k) * ldB + colBlock + j * 8;
        uint32_t d = k * 272 + j * 16;
        cp16(sb + OFF_BHI + d, Bhi + g);
        cp16(sb + OFF_BLO + d, Blo + g);
    }
}

// ---------------- GEMM core: 128x128 tile, BK=32, 3-term split ----------------
// BT=false: B from [n][k]; BT=true: B from [k][n] via ldmatrix.trans.
// B fragments double-buffered across the np loop to hide LDSM latency.
template<bool BT>
__device__ __forceinline__ void tc_core(
    const __nv_bfloat16* __restrict__ Ahi, const __nv_bfloat16* __restrict__ Alo,
    const __nv_bfloat16* __restrict__ Bhi, const __nv_bfloat16* __restrict__ Blo,
    int K_total, int ldB, int rowBlock, int colBlock,
    float acc[2][8][4])
{
    const int tid  = threadIdx.x;
    const int lane = tid & 31;
    const int wid  = tid >> 5;
    const int warpRow = wid & 3;
    const int warpCol = wid >> 2;

    const uint32_t sbase = smem_u32(dsmem);

#pragma unroll
    for (int mt = 0; mt < 2; mt++)
#pragma unroll
        for (int nt = 0; nt < 8; nt++)
#pragma unroll
            for (int e = 0; e < 4; e++) acc[mt][nt][e] = 0.f;

    // ldmatrix per-thread byte offsets
    const uint32_t aOff = ((warpRow * 32 + (lane & 15)) * LDA + ((lane >> 4) << 3)) * 2;
    const uint32_t bOffK = ((warpCol * 64 + ((lane >> 4) << 3) + (lane & 7)) * LDA
                           + (((lane >> 3) & 1) << 3)) * 2;
    const uint32_t bOffT = ((lane & 15) * LDBT + warpCol * 64 + ((lane >> 4) << 3)) * 2;

    const int ntiles = K_total >> 5;

    // prologue: stages 0,1
    ld_tileA(sbase, Ahi, Alo, K_total, rowBlock, 0, tid);
    if (BT) ld_tileB_t(sbase, Bhi, Blo, ldB, colBlock, 0, tid);
    else    ld_tileB_k(sbase, Bhi, Blo, ldB, colBlock, 0, tid);
    CP_COMMIT();
    ld_tileA(sbase + STAGE_BYTES, Ahi, Alo, K_total, rowBlock, 32, tid);
    if (BT) ld_tileB_t(sbase + STAGE_BYTES, Bhi, Blo, ldB, colBlock, 32, tid);
    else    ld_tileB_k(sbase + STAGE_BYTES, Bhi, Blo, ldB, colBlock, 32, tid);
    CP_COMMIT();

    for (int kt = 0; kt < ntiles; kt++) {
        if (kt + 1 < ntiles) { CP_WAIT1(); } else { CP_WAIT0(); }
        __syncthreads();

        const uint32_t sb = sbase + (kt & 1) * STAGE_BYTES;
#pragma unroll
        for (int ks = 0; ks < 2; ks++) {
            const int kb = ks * 16;
            uint32_t ah[2][4], al[2][4];
            uint32_t bh[2][4], bl[2][4];   // double-buffered B fragments

            // Issue A hi/lo and B(np=0) loads back-to-back: one exposed latency.
#pragma unroll
            for (int mt = 0; mt < 2; mt++) {
                uint32_t ad = sb + aOff + (mt * 16 * LDA + kb) * 2;
                LDMATRIX_X4(ah[mt][0], ah[mt][1], ah[mt][2], ah[mt][3], ad + OFF_AHI);
                LDMATRIX_X4(al[mt][0], al[mt][1], al[mt][2], al[mt][3], ad + OFF_ALO);
            }
            if (BT) {
                uint32_t bd = sb + bOffT + (kb * LDBT) * 2;
                LDMATRIX_X4_T(bh[0][0], bh[0][1], bh[0][2], bh[0][3], bd + OFF_BHI);
                LDMATRIX_X4_T(bl[0][0], bl[0][1], bl[0][2], bl[0][3], bd + OFF_BLO);
            } else {
                uint32_t bd = sb + bOffK + (kb) * 2;
                LDMATRIX_X4(bh[0][0], bh[0][1], bh[0][2], bh[0][3], bd + OFF_BHI);
                LDMATRIX_X4(bl[0][0], bl[0][1], bl[0][2], bl[0][3], bd + OFF_BLO);
            }

#pragma unroll
            for (int np = 0; np < 4; np++) {
                const int cur = np & 1;
                const int nxt = cur ^ 1;
                // Prefetch B(np+1) while MMAs consume B(np).
                if (np < 3) {
                    if (BT) {
                        uint32_t bd = sb + bOffT + (kb * LDBT + (np + 1) * 16) * 2;
                        LDMATRIX_X4_T(bh[nxt][0], bh[nxt][1], bh[nxt][2], bh[nxt][3], bd + OFF_BHI);
                        LDMATRIX_X4_T(bl[nxt][0], bl[nxt][1], bl[nxt][2], bl[nxt][3], bd + OFF_BLO);
                    } else {
                        uint32_t bd = sb + bOffK + ((np + 1) * 16 * LDA + kb) * 2;
                        LDMATRIX_X4(bh[nxt][0], bh[nxt][1], bh[nxt][2], bh[nxt][3], bd + OFF_BHI);
                        LDMATRIX_X4(bl[nxt][0], bl[nxt][1], bl[nxt][2], bl[nxt][3], bd + OFF_BLO);
                    }
                }
#pragma unroll
                for (int half = 0; half < 2; half++) {
                    uint32_t bh0 = bh[cur][half * 2], bh1 = bh[cur][half * 2 + 1];
                    uint32_t bl0 = bl[cur][half * 2], bl1 = bl[cur][half * 2 + 1];
#pragma unroll
                    for (int mt = 0; mt < 2; mt++) {
                        int nt = np * 2 + half;
                        mma_bf16(acc[mt][nt], ah[mt][0], ah[mt][1], ah[mt][2], ah[mt][3], bh0, bh1);
                        mma_bf16(acc[mt][nt], ah[mt][0], ah[mt][1], ah[mt][2], ah[mt][3], bl0, bl1);
                        mma_bf16(acc[mt][nt], al[mt][0], al[mt][1], al[mt][2], al[mt][3], bh0, bh1);
                    }
                }
            }
        }
        __syncthreads();

        if (kt + 2 < ntiles) {
            const uint32_t sb2 = sbase + (kt & 1) * STAGE_BYTES;
            const int k0 = (kt + 2) * 32;
            ld_tileA(sb2, Ahi, Alo, K_total, rowBlock, k0, tid);
            if (BT) ld_tileB_t(sb2, Bhi, Blo, ldB, colBlock, k0, tid);
            else    ld_tileB_k(sb2, Bhi, Blo, ldB, colBlock, k0, tid);
            CP_COMMIT();
        }
    }
}

// ---------------- Stage 0: split inputs + weights to bf16 hi/lo ----------------
__global__ __launch_bounds__(256) void pre_kernel(
    const float* __restrict__ q, const float* __restrict__ k, const float* __restrict__ v,
    const float* __restrict__ Wq, const float* __restrict__ Wk, const float* __restrict__ Wv)
{
    const int z = blockIdx.z;
    const float* src;
    __nv_bfloat16 *hi, *lo;
    size_t n4;
    if (z < 3) {
        src = (z == 0) ? q : (z == 1) ? k : v;
        hi = g_Ihi + (size_t)z * RC; lo = g_Ilo + (size_t)z * RC;
        n4 = RC / 4;
    } else {
        int w = z - 3;
        src = (w == 0) ? Wq : (w == 1) ? Wk : Wv;
        hi = g_Whi + (size_t)w * CH * CH; lo = g_Wlo + (size_t)w * CH * CH;
        n4 = (size_t)CH * CH / 4;
    }
    size_t i4 = (size_t)blockIdx.x * 256 + threadIdx.x;
    if (i4 >= n4) return;
    float4 val = ((const float4*)src)[i4];
    uint32_t h01, l01, h23, l23;
    split2(val.x, val.y, h01, l01);
    split2(val.z, val.w, h23, l23);
    *(uint2*)(hi + i4 * 4) = make_uint2(h01, h23);
    *(uint2*)(lo + i4 * 4) = make_uint2(l01, l23);
}

// ---------------- Stage 1: projections (output split bf16; Q pre-scaled) -------
__global__ __launch_bounds__(256, 2) void proj_kernel(
    const float* __restrict__ bq, const float* __restrict__ bk, const float* __restrict__ bv)
{
    const int z = blockIdx.z;
    const __nv_bfloat16* Ahi = g_Ihi + (size_t)z * RC;
    const __nv_bfloat16* Alo = g_Ilo + (size_t)z * RC;
    const __nv_bfloat16* Bhi = g_Whi + (size_t)z * CH * CH;
    const __nv_bfloat16* Blo = g_Wlo + (size_t)z * CH * CH;
    const float* bias = (z == 0) ? bq : (z == 1) ? bk : bv;
    __nv_bfloat16* Chi = (z == 0) ? g_Qhi : (z == 1) ? g_Khi : g_Vhi;
    __nv_bfloat16* Clo = (z == 0) ? g_Qlo : (z == 1) ? g_Klo : g_Vlo;
    const float alpha = (z == 0) ? SCALE : 1.0f;

    const int rowBlock = blockIdx.y * 128;
    const int colBlock = blockIdx.x * 128;

    float acc[2][8][4];
    tc_core<true>(Ahi, Alo, Bhi, Blo, CH, CH, rowBlock, colBlock, acc);

    const int lane = threadIdx.x & 31;
    const int wid  = threadIdx.x >> 5;
    const int warpRow = wid & 3, warpCol = wid >> 2;
#pragma unroll
    for (int mt = 0; mt < 2; mt++) {
#pragma unroll
        for (int nt = 0; nt < 8; nt++) {
            int row = rowBlock + warpRow * 32 + mt * 16 + (lane >> 2);
            int col = colBlock + warpCol * 64 + nt * 8 + (lane & 3) * 2;
            float2 b = *(const float2*)(bias + col);
            float x0 = (acc[mt][nt][0] + b.x) * alpha;
            float y0 = (acc[mt][nt][1] + b.y) * alpha;
            float x1 = (acc[mt][nt][2] + b.x) * alpha;
            float y1 = (acc[mt][nt][3] + b.y) * alpha;
            uint32_t h, l;
            split2(x0, y0, h, l);
            *(uint32_t*)(Chi + (size_t)row * CH + col) = h;
            *(uint32_t*)(Clo + (size_t)row * CH + col) = l;
            split2(x1, y1, h, l);
            *(uint32_t*)(Chi + (size_t)(row + 8) * CH + col) = h;
            *(uint32_t*)(Clo + (size_t)(row + 8) * CH + col) = l;
        }
    }
}

// ---------------- Stage 2: S = Q * K^T (scale already folded into Q) ----------
__global__ __launch_bounds__(256, 2) void qk_kernel()
{
    const int z = blockIdx.z;
    const size_t po = (size_t)z * SEQ * CH;
    float* S = g_S + (size_t)z * SEQ * SEQ;
    const int rowBlock = blockIdx.y * 128;
    const int colBlock = blockIdx.x * 128;

    float acc[2][8][4];
    tc_core<false>(g_Qhi + po, g_Qlo + po, g_Khi + po, g_Klo + po,
                   CH, CH, rowBlock, colBlock, acc);

    const int lane = threadIdx.x & 31;
    const int wid  = threadIdx.x >> 5;
    const int warpRow = wid & 3, warpCol = wid >> 2;
#pragma unroll
    for (int mt = 0; mt < 2; mt++) {
#pragma unroll
        for (int nt = 0; nt < 8; nt++) {
            int row = rowBlock + warpRow * 32 + mt * 16 + (lane >> 2);
            int col = colBlock + warpCol * 64 + nt * 8 + (lane & 3) * 2;
            *(float2*)(S + (size_t)row * SEQ + col) =
                make_float2(acc[mt][nt][0], acc[mt][nt][1]);
            *(float2*)(S + (size_t)(row + 8) * SEQ + col) =
                make_float2(acc[mt][nt][2], acc[mt][nt][3]);
        }
    }
}

// ---------------- Stage 3: softmax -> split bf16 probs ----------------
__global__ __launch_bounds__(256) void softmax_kernel()
{
    __shared__ float red[8];
    const size_t ro = (size_t)blockIdx.x * SEQ;
    const float* row = g_S + ro;
    const int tid = threadIdx.x;

    float vals[8];
    float m = -3.0e38f;
#pragma unroll
    for (int i = 0; i < 8; i++) {
        vals[i] = row[tid + i * 256];
        m = fmaxf(m, vals[i]);
    }
#pragma unroll
    for (int o = 16; o; o >>= 1) m = fmaxf(m, __shfl_xor_sync(0xffffffffu, m, o));
    if ((tid & 31) == 0) red[tid >> 5] = m;
    __syncthreads();
    float bm = red[0];
#pragma unroll
    for (int i = 1; i < 8; i++) bm = fmaxf(bm, red[i]);
    __syncthreads();

    float s = 0.f;
#pragma unroll
    for (int i = 0; i < 8; i++) {
        vals[i] = __expf(vals[i] - bm);
        s += vals[i];
    }
#pragma unroll
    for (int o = 16; o; o >>= 1) s += __shfl_xor_sync(0xffffffffu, s, o);
    if ((tid & 31) == 0) red[tid >> 5] = s;
    __syncthreads();
    float tot = 0.f;
#pragma unroll
    for (int i = 0; i < 8; i++) tot += red[i];
    float inv = 1.0f / tot;
#pragma unroll
    for (int i = 0; i < 8; i++) {
        float p = vals[i] * inv;
        __nv_bfloat16 h = __float2bfloat16(p);
        __nv_bfloat16 l = __float2bfloat16(p - __bfloat162float(h));
        g_Shi[ro + tid + i * 256] = h;
        g_Slo[ro + tid + i * 256] = l;
    }
}

// ---------------- Stage 4: O = P * V ----------------
__global__ __launch_bounds__(256, 2) void pv_kernel(float* __restrict__ out)
{
    const int z = blockIdx.z;
    const size_t so = (size_t)z * SEQ * SEQ;
    const size_t vo = (size_t)z * SEQ * CH;
    const int rowBlock = blockIdx.y * 128;
    const int colBlock = blockIdx.x * 128;

    float acc[2][8][4];
    tc_core<true>(g_Shi + so, g_Slo + so, g_Vhi + vo, g_Vlo + vo,
                  SEQ, CH, rowBlock, colBlock, acc);

    float* O = out + vo;
    const int lane = threadIdx.x & 31;
    const int wid  = threadIdx.x >> 5;
    const int warpRow = wid & 3, warpCol = wid >> 2;
#pragma unroll
    for (int mt = 0; mt < 2; mt++) {
#pragma unroll
        for (int nt = 0; nt < 8; nt++) {
            int row = rowBlock + warpRow * 32 + mt * 16 + (lane >> 2);
            int col = colBlock + warpCol * 64 + nt * 8 + (lane & 3) * 2;
            *(float2*)(O + (size_t)row * CH + col) =
                make_float2(acc[mt][nt][0], acc[mt][nt][1]);
            *(float2*)(O + (size_t)(row + 8) * CH + col) =
                make_float2(acc[mt][nt][2], acc[mt][nt][3]);
        }
    }
}

// ---------------------------------------------------------------------------
extern "C" void kernel_launch(void* const* d_in, const int* in_sizes, int n_in,
                              void* d_out, int out_size)
{
    const float* q  = (const float*)d_in[0];
    const float* k  = (const float*)d_in[1];
    const float* v  = (const float*)d_in[2];
    const float* Wq = (const float*)d_in[3];
    const float* bq = (const float*)d_in[4];
    const float* Wk = (const float*)d_in[5];
    const float* bk = (const float*)d_in[6];
    const float* Wv = (const float*)d_in[7];
    const float* bv = (const float*)d_in[8];
    float* out = (float*)d_out;

    static int configured = 0;
    if (!configured) {
        cudaFuncSetAttribute(proj_kernel, cudaFuncAttributeMaxDynamicSharedMemorySize, SMEM_TOTAL);
        cudaFuncSetAttribute(qk_kernel,   cudaFuncAttributeMaxDynamicSharedMemorySize, SMEM_TOTAL);
        cudaFuncSetAttribute(pv_kernel,   cudaFuncAttributeMaxDynamicSharedMemorySize, SMEM_TOTAL);
        configured = 1;
    }

    dim3 gPre(8192, 1, 6);
    pre_kernel<<<gPre, 256>>>(q, k, v, Wq, Wk, Wv);

    dim3 gProj(CH / 128, ROWS / 128, 3);      // (4, 128, 3)
    proj_kernel<<<gProj, 256, SMEM_TOTAL>>>(bq, bk, bv);

    dim3 gQK(SEQ / 128, SEQ / 128, BATCH);    // (16, 16, 8)
    qk_kernel<<<gQK, 256, SMEM_TOTAL>>>();

    softmax_kernel<<<ROWS, 256>>>();          // 16384 rows

    dim3 gPV(CH / 128, SEQ / 128, BATCH);     // (4, 16, 8)
    pv_kernel<<<gPV, 256, SMEM_TOTAL>>>(out);
}